// round 13
// baseline (speedup 1.0000x reference)
#include <cuda_runtime.h>
#include <cuda_bf16.h>
#include <cstdint>

#define B   16
#define NQ  512
#define NK  1024
#define CIN 128
#define H   8
#define D   64
#define HD  512
#define LOG2E 1.4426950408889634f

// ---------------- device scratch (bf16 everywhere) ----------------
__device__ __align__(256) __nv_bfloat16 g_Qb[B * H * NQ * D];    // scaled by qscale
__device__ __align__(256) __nv_bfloat16 g_Kb[B * H * NK * D];
__device__ __align__(256) __nv_bfloat16 g_Vh[B * H * NK * D];
__device__ __align__(256) __nv_bfloat16 g_Vl[B * H * NK * D];
// split inputs / transposed split weights
__device__ __align__(256) __nv_bfloat16 g_qXh[B * NQ * CIN], g_qXl[B * NQ * CIN];
__device__ __align__(256) __nv_bfloat16 g_kXh[B * NK * CIN], g_kXl[B * NK * CIN];
__device__ __align__(256) __nv_bfloat16 g_Wth[3 * HD * CIN], g_Wtl[3 * HD * CIN];

// ============================ helpers ============================
__device__ __forceinline__ uint32_t smem_u32(const void* p) {
    uint32_t a;
    asm("{ .reg .u64 t; cvta.to.shared.u64 t, %1; cvt.u32.u64 %0, t; }" : "=r"(a) : "l"(p));
    return a;
}
#define SWZ(off) ((off) ^ (((off) >> 3) & 0x70))

__device__ __forceinline__ uint32_t packbf(float x, float y) {  // lo=x, hi=y
    uint32_t r; asm("cvt.rn.bf16x2.f32 %0,%1,%2;" : "=r"(r) : "f"(y), "f"(x)); return r;
}
__device__ __forceinline__ float ex2(float x) {
    float r; asm("ex2.approx.f32 %0,%1;" : "=f"(r) : "f"(x)); return r;
}
__device__ __forceinline__ float bfround(float x) {
    return __bfloat162float(__float2bfloat16(x));
}
__device__ __forceinline__ void ldsm4(uint32_t (&r)[4], uint32_t a) {
    asm volatile("ldmatrix.sync.aligned.m8n8.x4.shared.b16 {%0,%1,%2,%3},[%4];"
        : "=r"(r[0]), "=r"(r[1]), "=r"(r[2]), "=r"(r[3]) : "r"(a));
}
__device__ __forceinline__ void ldsm4t(uint32_t (&r)[4], uint32_t a) {
    asm volatile("ldmatrix.sync.aligned.m8n8.x4.trans.shared.b16 {%0,%1,%2,%3},[%4];"
        : "=r"(r[0]), "=r"(r[1]), "=r"(r[2]), "=r"(r[3]) : "r"(a));
}
__device__ __forceinline__ void mma16816(float (&c)[4], const uint32_t (&a)[4],
                                         uint32_t b0, uint32_t b1) {
    asm volatile("mma.sync.aligned.m16n8k16.row.col.f32.bf16.bf16.f32 "
        "{%0,%1,%2,%3},{%4,%5,%6,%7},{%8,%9},{%0,%1,%2,%3};"
        : "+f"(c[0]), "+f"(c[1]), "+f"(c[2]), "+f"(c[3])
        : "r"(a[0]), "r"(a[1]), "r"(a[2]), "r"(a[3]), "r"(b0), "r"(b1));
}

// ============================ converters ============================
// fp32 X -> bf16 hi/lo, row layout unchanged [row][128]
__global__ __launch_bounds__(256)
void convX_kernel(const float* __restrict__ X, int which /*0=q,1=k*/, int n4)
{
    int i = blockIdx.x * 256 + threadIdx.x;
    if (i >= n4) return;
    __nv_bfloat16* Xh = which ? g_kXh : g_qXh;
    __nv_bfloat16* Xl = which ? g_kXl : g_qXl;
    float4 v = ((const float4*)X)[i];
    float h0 = bfround(v.x), h1 = bfround(v.y), h2 = bfround(v.z), h3 = bfround(v.w);
    ((uint2*)Xh)[i] = make_uint2(packbf(h0, h1), packbf(h2, h3));
    ((uint2*)Xl)[i] = make_uint2(packbf(v.x - h0, v.y - h1), packbf(v.z - h2, v.w - h3));
}

// fp32 W[128k][512n] -> transposed bf16 hi/lo Wt[512n][128k]
__global__ __launch_bounds__(256)
void convW_kernel(const float* __restrict__ W, int which)
{
    int i = blockIdx.x * 256 + threadIdx.x;      // 0 .. 128*128-1
    int k = i >> 7, n4 = (i & 127) * 4;
    __nv_bfloat16* Wth = g_Wth + which * HD * CIN;
    __nv_bfloat16* Wtl = g_Wtl + which * HD * CIN;
    float4 v = *(const float4*)&W[k * HD + n4];
    float vv[4] = {v.x, v.y, v.z, v.w};
    #pragma unroll
    for (int e = 0; e < 4; e++) {
        float hh = bfround(vv[e]);
        Wth[(n4 + e) * CIN + k] = __float2bfloat16(hh);
        Wtl[(n4 + e) * CIN + k] = __float2bfloat16(vv[e] - hh);
    }
}

// ============================ tensor-core projection ============================
// C[128m x 64n] = X[128m x 128k] . Wt[64n x 128k]^T via 3-term bf16 split.
// 256 threads = 8 warps; warp w owns rows [Mbase+16w, +16) x all 64 n.
// Only W lives in smem (hi+lo = 32KB static, two 64-k panels each);
// X A-fragments are loaded directly from global (attn-Q pattern).
__global__ __launch_bounds__(256)
void projmma_kernel(const float* __restrict__ bias, int mode /*0=Q,1=K,2=V*/,
                    int Nrows, float scale)
{
    __shared__ __align__(128) uint8_t smWh[16384];   // [2 panels][64 n][128B]
    __shared__ __align__(128) uint8_t smWl[16384];

    const __nv_bfloat16* Xh = (mode == 0) ? g_qXh : g_kXh;
    const __nv_bfloat16* Xl = (mode == 0) ? g_qXl : g_kXl;
    const __nv_bfloat16* Wth = g_Wth + mode * HD * CIN;
    const __nv_bfloat16* Wtl = g_Wtl + mode * HD * CIN;

    const int tid = threadIdx.x;
    const int w = tid >> 5, lane = tid & 31;
    const int g = lane >> 2, t = lane & 3;
    const long Mbase = (long)blockIdx.x * 128;
    const int Nbase = blockIdx.y * 64;

    // stage W hi/lo: per matrix 64 rows x 128 bf16 = 1024 uint4 -> 4 iters
    #pragma unroll
    for (int i = 0; i < 4; i++) {
        int p = tid + i * 256;            // 0..1023
        int r = p >> 4, j = p & 15;       // n row, 16B k-group
        uint32_t dst = (uint32_t)(j >> 3) * 8192 + SWZ((uint32_t)r * 128 + (j & 7) * 16);
        *(uint4*)(smWh + dst) = *(const uint4*)&Wth[(size_t)(Nbase + r) * CIN + j * 8];
        *(uint4*)(smWl + dst) = *(const uint4*)&Wtl[(size_t)(Nbase + r) * CIN + j * 8];
    }

    // preload X A-fragments (8 k-chunks, hi+lo) directly from global
    uint32_t ah[8][4], al[8][4];
    {
        const size_t r0 = (size_t)(Mbase + w * 16 + g) * CIN;
        const size_t r8 = (size_t)(Mbase + w * 16 + g + 8) * CIN;
        #pragma unroll
        for (int kc = 0; kc < 8; kc++) {
            int c0 = kc * 16 + 2 * t;
            ah[kc][0] = *(const uint32_t*)&Xh[r0 + c0];
            ah[kc][1] = *(const uint32_t*)&Xh[r8 + c0];
            ah[kc][2] = *(const uint32_t*)&Xh[r0 + c0 + 8];
            ah[kc][3] = *(const uint32_t*)&Xh[r8 + c0 + 8];
            al[kc][0] = *(const uint32_t*)&Xl[r0 + c0];
            al[kc][1] = *(const uint32_t*)&Xl[r8 + c0];
            al[kc][2] = *(const uint32_t*)&Xl[r0 + c0 + 8];
            al[kc][3] = *(const uint32_t*)&Xl[r8 + c0 + 8];
        }
    }
    __syncthreads();

    float acc[8][4];
    #pragma unroll
    for (int nn = 0; nn < 8; nn++)
        #pragma unroll
        for (int i = 0; i < 4; i++) acc[nn][i] = 0.f;

    const int bRow = (lane & 7) + ((lane >> 4) & 1) * 8;
    const int bHalf = (lane >> 3) & 1;
    const uint32_t sbh = smem_u32(smWh);
    const uint32_t sbl = smem_u32(smWl);

    #pragma unroll
    for (int kc = 0; kc < 8; kc++) {
        const uint32_t pan = (uint32_t)(kc >> 2) * 8192;
        const uint32_t kb = (uint32_t)(kc & 3) * 32;
        #pragma unroll
        for (int nn = 0; nn < 4; nn++) {
            uint32_t roff = pan + SWZ((uint32_t)(nn * 16 + bRow) * 128 + kb + bHalf * 16);
            uint32_t bh[4], bl[4];
            ldsm4(bh, sbh + roff);
            ldsm4(bl, sbl + roff);
            mma16816(acc[2 * nn],     ah[kc], bh[0], bh[1]);
            mma16816(acc[2 * nn + 1], ah[kc], bh[2], bh[3]);
            mma16816(acc[2 * nn],     al[kc], bh[0], bh[1]);
            mma16816(acc[2 * nn + 1], al[kc], bh[2], bh[3]);
            mma16816(acc[2 * nn],     ah[kc], bl[0], bl[1]);
            mma16816(acc[2 * nn + 1], ah[kc], bl[2], bl[3]);
        }
    }

    // epilogue: +bias, *scale, emit bf16 (Q/K) or hi/lo bf16 (V)
    #pragma unroll
    for (int half = 0; half < 2; half++) {
        long row = Mbase + w * 16 + g + half * 8;
        int bb = (int)(row / Nrows);
        int lr = (int)(row % Nrows);
        #pragma unroll
        for (int nn = 0; nn < 8; nn++) {
            int col = Nbase + nn * 8 + 2 * t;
            float2 bs = *(const float2*)&bias[col];
            float v0 = (acc[nn][half * 2]     + bs.x) * scale;
            float v1 = (acc[nn][half * 2 + 1] + bs.y) * scale;
            int hh = col >> 6, d = col & 63;
            size_t o = ((size_t)(bb * H + hh) * Nrows + lr) * 64 + d;
            if (mode == 2) {
                float h0 = bfround(v0), h1 = bfround(v1);
                *(uint32_t*)&g_Vh[o] = packbf(h0, h1);
                *(uint32_t*)&g_Vl[o] = packbf(v0 - h0, v1 - h1);
            } else if (mode == 1) {
                *(uint32_t*)&g_Kb[o] = packbf(v0, v1);
            } else {
                *(uint32_t*)&g_Qb[o] = packbf(v0, v1);
            }
        }
    }
}

// ============================ mma.sync attention ============================
// 256 threads = 8 warps; block = 128 queries x one (b,h); 64-key tiles.
// All inputs pre-packed bf16: staging is pure 16B copies.
__global__ __launch_bounds__(256)
void attn_kernel(const float* __restrict__ c_mask, float* __restrict__ out)
{
    __shared__ __align__(128) uint8_t smK [64 * 128];  // bf16 [key][64d]
    __shared__ __align__(128) uint8_t smVh[64 * 128];
    __shared__ __align__(128) uint8_t smVl[64 * 128];
    __shared__ float msf[64];

    const int tid  = threadIdx.x;
    const int w    = tid >> 5;
    const int lane = tid & 31;
    const int g = lane >> 2, t = lane & 3;
    const int h = blockIdx.y, b = blockIdx.z;
    const long bh = (long)b * H + h;
    const int q0 = blockIdx.x * 128;

    // preload Q A-fragments straight from bf16 global
    uint32_t qa[4][4];
    {
        const __nv_bfloat16* Qb = &g_Qb[(bh * NQ + q0 + w * 16) * D];
        #pragma unroll
        for (int kc = 0; kc < 4; kc++) {
            qa[kc][0] = *(const uint32_t*)&Qb[ g      * D + kc * 16 + 2 * t];
            qa[kc][1] = *(const uint32_t*)&Qb[(g + 8) * D + kc * 16 + 2 * t];
            qa[kc][2] = *(const uint32_t*)&Qb[ g      * D + kc * 16 + 8 + 2 * t];
            qa[kc][3] = *(const uint32_t*)&Qb[(g + 8) * D + kc * 16 + 8 + 2 * t];
        }
    }

    float oacc[8][4];
    #pragma unroll
    for (int n = 0; n < 8; n++)
        #pragma unroll
        for (int i = 0; i < 4; i++) oacc[n][i] = 0.f;
    float lg = 0.f, lh = 0.f;

    const float* __restrict__ mb = c_mask + (long)b * NK;
    const uint32_t skb = smem_u32(smK);
    const uint32_t svh = smem_u32(smVh);
    const uint32_t svl = smem_u32(smVl);

    const int kRow = (lane & 7) + ((lane >> 4) & 1) * 8;   // S B-frag (non-trans)
    const int kCol = (lane >> 3) & 1;
    const int vRow = (lane & 7) + ((lane >> 3) & 1) * 8;   // PV B-frag (trans)
    const int vCol = lane >> 4;

    #pragma unroll 1
    for (int kt = 0; kt < NK / 64; kt++) {
        __syncthreads();

        // stage K / Vh / Vl tiles: pure swizzled 16B copies
        {
            const __nv_bfloat16* Kb  = &g_Kb[(bh * NK + kt * 64) * D];
            const __nv_bfloat16* Vhb = &g_Vh[(bh * NK + kt * 64) * D];
            const __nv_bfloat16* Vlb = &g_Vl[(bh * NK + kt * 64) * D];
            #pragma unroll
            for (int i = 0; i < 2; i++) {
                int p = tid + i * 256;
                int row = p >> 3, j = p & 7;
                uint32_t dst = SWZ((uint32_t)row * 128 + j * 16);
                *(uint4*)(smK  + dst) = *(const uint4*)&Kb [row * D + j * 8];
                *(uint4*)(smVh + dst) = *(const uint4*)&Vhb[row * D + j * 8];
                *(uint4*)(smVl + dst) = *(const uint4*)&Vlb[row * D + j * 8];
            }
        }
        if (tid < 64)
            msf[tid] = (-100000.f * LOG2E) * (1.f - mb[kt * 64 + tid]);
        __syncthreads();

        // ---- S = Q . K^T ----
        float sacc[8][4];
        #pragma unroll
        for (int n = 0; n < 8; n++)
            #pragma unroll
            for (int i = 0; i < 4; i++) sacc[n][i] = 0.f;

        #pragma unroll
        for (int kc = 0; kc < 4; kc++) {
            #pragma unroll
            for (int kp = 0; kp < 4; kp++) {
                uint32_t r[4];
                ldsm4(r, skb + SWZ((uint32_t)(16 * kp + kRow) * 128 + (2 * kc + kCol) * 16));
                mma16816(sacc[2 * kp],     qa[kc], r[0], r[1]);
                mma16816(sacc[2 * kp + 1], qa[kc], r[2], r[3]);
            }
        }

        // ---- softmax: p = ex2(s + m); build P fragments hi/lo ----
        uint32_t pahi[4][4], palo[4][4];
        #pragma unroll
        for (int n = 0; n < 8; n++) {
            float2 mv = *(const float2*)&msf[8 * n + 2 * t];
            float p0 = ex2(sacc[n][0] + mv.x);
            float p1 = ex2(sacc[n][1] + mv.y);
            float p2 = ex2(sacc[n][2] + mv.x);
            float p3 = ex2(sacc[n][3] + mv.y);
            lg += p0 + p1;
            lh += p2 + p3;
            float h0 = bfround(p0), h1 = bfround(p1);
            float h2 = bfround(p2), h3 = bfround(p3);
            int kc = n >> 1, hi = (n & 1) * 2;
            pahi[kc][hi]     = packbf(h0, h1);
            pahi[kc][hi + 1] = packbf(h2, h3);
            palo[kc][hi]     = packbf(p0 - h0, p1 - h1);
            palo[kc][hi + 1] = packbf(p2 - h2, p3 - h3);
        }

        // ---- O += Phi.Vhi + Plo.Vhi + Phi.Vlo ----
        #pragma unroll
        for (int kc = 0; kc < 4; kc++) {
            uint32_t vh[8][2], vl[8][2];
            #pragma unroll
            for (int dp = 0; dp < 4; dp++) {
                uint32_t off = SWZ((uint32_t)(16 * kc + vRow) * 128 + (2 * dp + vCol) * 16);
                uint32_t r[4];
                ldsm4t(r, svh + off);
                vh[2 * dp][0] = r[0]; vh[2 * dp][1] = r[1];
                vh[2 * dp + 1][0] = r[2]; vh[2 * dp + 1][1] = r[3];
                ldsm4t(r, svl + off);
                vl[2 * dp][0] = r[0]; vl[2 * dp][1] = r[1];
                vl[2 * dp + 1][0] = r[2]; vl[2 * dp + 1][1] = r[3];
            }
            #pragma unroll
            for (int n = 0; n < 8; n++) {
                mma16816(oacc[n], pahi[kc], vh[n][0], vh[n][1]);
                mma16816(oacc[n], palo[kc], vh[n][0], vh[n][1]);
                mma16816(oacc[n], pahi[kc], vl[n][0], vl[n][1]);
            }
        }
    }

    // ---- finalize ----
    lg += __shfl_xor_sync(0xffffffffu, lg, 1);
    lg += __shfl_xor_sync(0xffffffffu, lg, 2);
    lh += __shfl_xor_sync(0xffffffffu, lh, 1);
    lh += __shfl_xor_sync(0xffffffffu, lh, 2);
    float ig = 1.f / lg, ih = 1.f / lh;

    float* og = &out[((long)b * NQ + q0 + w * 16 + g)     * HD + h * D];
    float* oh = &out[((long)b * NQ + q0 + w * 16 + g + 8) * HD + h * D];
    #pragma unroll
    for (int n = 0; n < 8; n++) {
        *(float2*)&og[8 * n + 2 * t] = make_float2(oacc[n][0] * ig, oacc[n][1] * ig);
        *(float2*)&oh[8 * n + 2 * t] = make_float2(oacc[n][2] * ih, oacc[n][3] * ih);
    }
}

// ---------------------------------------------------------------------------
// Pure kernel launches only — no runtime API calls (graph-capture safe).
// ---------------------------------------------------------------------------
extern "C" void kernel_launch(void* const* d_in, const int* in_sizes, int n_in,
                              void* d_out, int out_size)
{
    const float* query  = (const float*)d_in[0];
    const float* key    = (const float*)d_in[1];
    const float* c_mask = (const float*)d_in[2];
    const float* Wq     = (const float*)d_in[3];
    const float* bq     = (const float*)d_in[4];
    const float* Wk     = (const float*)d_in[5];
    const float* bk     = (const float*)d_in[6];
    const float* Wv     = (const float*)d_in[7];
    const float* bv     = (const float*)d_in[8];
    float* out = (float*)d_out;

    const float qscale = 0.125f * LOG2E;   // 1/sqrt(D) * log2(e)

    // split-convert inputs and weights
    convX_kernel<<<(B * NQ * CIN / 4 + 255) / 256, 256>>>(query, 0, B * NQ * CIN / 4);
    convX_kernel<<<(B * NK * CIN / 4 + 255) / 256, 256>>>(key,   1, B * NK * CIN / 4);
    convW_kernel<<<64, 256>>>(Wq, 0);
    convW_kernel<<<64, 256>>>(Wk, 1);
    convW_kernel<<<64, 256>>>(Wv, 2);

    // tensor-core projections (static 32KB smem — no attribute calls needed)
    projmma_kernel<<<dim3(B * NQ / 128, HD / 64), 256>>>(bq, 0, NQ, qscale);
    projmma_kernel<<<dim3(B * NK / 128, HD / 64), 256>>>(bk, 1, NK, 1.0f);
    projmma_kernel<<<dim3(B * NK / 128, HD / 64), 256>>>(bv, 2, NK, 1.0f);

    // fused attention
    dim3 grid(NQ / 128, H, B);
    attn_kernel<<<grid, 256>>>(c_mask, out);
}